// round 2
// baseline (speedup 1.0000x reference)
#include <cuda_runtime.h>

#define LS 4104           // padded time stride for activation buffers
#define NB 32
#define NT 4096
#define ND 256
#define NK 1024

typedef unsigned long long ull;

// ---------------- f32x2 helpers --------------------------------------------------
__device__ __forceinline__ ull ffma2(ull a, ull b, ull c) {
    ull d;
    asm("fma.rn.f32x2 %0, %1, %2, %3;" : "=l"(d) : "l"(a), "l"(b), "l"(c));
    return d;
}
__device__ __forceinline__ ull pack2(float lo, float hi) {
    ull r;
    asm("mov.b64 %0, {%1, %2};" : "=l"(r) : "f"(lo), "f"(hi));
    return r;
}
__device__ __forceinline__ void unpack2(ull v, float& lo, float& hi) {
    asm("mov.b64 {%0, %1}, %2;" : "=f"(lo), "=f"(hi) : "l"(v));
}

// ---------------- scratch (static device globals; no allocation) ----------------
__device__ float  g_bufA[(size_t)NB * ND * LS];
__device__ float  g_bufB[(size_t)NB * ND * LS];
__device__ double g_sum[ND];
__device__ double g_sumsq[ND];
__device__ float  g_scale[ND];
__device__ float  g_shift[ND];
__device__ float  g_cnorm[NK];
__device__ float  g_cnt[NK];
__device__ float  g_sumcur[(size_t)NK * ND];
__device__ float  g_n;

// ---------------- layer 1: conv 12 -> 256, k=4, pad=2, Lin=4096, Lout=4097 ------
__global__ __launch_bounds__(256) void conv1_kernel(
    const float* __restrict__ x, const float* __restrict__ w,
    const float* __restrict__ bias, float* __restrict__ out)
{
    __shared__ float in_s[12][68];
    __shared__ float w_s[64][49];
    __shared__ float o_s[64][65];
    __shared__ double ssum[64], ssq[64];

    const int tid = threadIdx.x;
    const int b = blockIdx.z, oc0 = blockIdx.y * 64, t0 = blockIdx.x * 64;
    const int ocl = tid & 63, tg = tid >> 6, tbase = tg * 16;
    const int Lout = 4097;

    for (int idx = tid; idx < 12 * 67; idx += 256) {
        int j = idx / 12, c = idx - j * 12;
        int ip = t0 - 2 + j;
        in_s[c][j] = ((unsigned)ip < 4096u) ? x[((size_t)b * NT + ip) * 12 + c] : 0.f;
    }
    for (int idx = tid; idx < 64 * 48; idx += 256) {
        int oc = idx / 48, r = idx - oc * 48;
        w_s[oc][r] = w[(size_t)(oc0 + oc) * 48 + r];
    }
    __syncthreads();

    float acc[16];
#pragma unroll
    for (int u = 0; u < 16; u++) acc[u] = 0.f;

#pragma unroll
    for (int c = 0; c < 12; c++) {
        float v[19];
#pragma unroll
        for (int u = 0; u < 19; u++) v[u] = in_s[c][tbase + u];
        float w0 = w_s[ocl][c * 4 + 0], w1 = w_s[ocl][c * 4 + 1];
        float w2 = w_s[ocl][c * 4 + 2], w3 = w_s[ocl][c * 4 + 3];
#pragma unroll
        for (int u = 0; u < 16; u++)
            acc[u] = fmaf(w3, v[u + 3], fmaf(w2, v[u + 2], fmaf(w1, v[u + 1], fmaf(w0, v[u], acc[u]))));
    }

    const float bv = bias[oc0 + ocl];
#pragma unroll
    for (int u = 0; u < 16; u++) acc[u] += bv;

    {
        double s = 0.0, q = 0.0;
#pragma unroll
        for (int u = 0; u < 16; u++)
            if (t0 + tbase + u < Lout) { double a = (double)acc[u]; s += a; q += a * a; }
        __syncthreads();
        if (tid < 64) { ssum[tid] = 0.0; ssq[tid] = 0.0; }
        __syncthreads();
        atomicAdd(&ssum[ocl], s);
        atomicAdd(&ssq[ocl], q);
        __syncthreads();
        if (tid < 64) {
            atomicAdd(&g_sum[oc0 + tid], ssum[tid]);
            atomicAdd(&g_sumsq[oc0 + tid], ssq[tid]);
        }
    }

    __syncthreads();
#pragma unroll
    for (int u = 0; u < 16; u++) o_s[ocl][tbase + u] = acc[u];
    __syncthreads();
    float* ob = out + ((size_t)b * ND + oc0) * LS + t0;
    for (int idx = tid; idx < 4096; idx += 256) {
        int oc = idx >> 6, t = idx & 63;
        if (t0 + t < Lout) ob[(size_t)oc * LS + t] = o_s[oc][t];
    }
}

// ---------------- generic D->D conv via packed f32x2 FMA -------------------------
// BN+ReLU applied to INPUT on the fly. Outputs paired (u, u+8) per accumulator.
// mode 0: write [b][c][t] (stride LS); mode 1: write z_e [b][t][d] into d_out
__global__ __launch_bounds__(256) void convDD_kernel(
    const float* __restrict__ in, const float* __restrict__ w,
    const float* __restrict__ bias, float* __restrict__ out,
    int Lin, int Lout, int pad, int mode, int do_stats)
{
    __shared__ ull in_s2[8][60];     // pair j -> (tile[j], tile[j+8]), j=0..58
    __shared__ ull w_s2[32][65];     // [c*4+k][oc] duplicated (w,w); padded rows
    __shared__ float o_s[64][65];
    __shared__ double ssum[64], ssq[64];

    const int tid = threadIdx.x;
    const int b = blockIdx.z, oc0 = blockIdx.y * 64, t0 = blockIdx.x * 64;
    const int ocl = tid & 63, tg = tid >> 6, tbase = tg * 16;

    ull acc2[8];
#pragma unroll
    for (int p = 0; p < 8; p++) acc2[p] = 0ull;

    const float* inb = in + (size_t)b * ND * LS;
    const int base = t0 - pad;

    for (int cc = 0; cc < 256; cc += 8) {
        __syncthreads();
        // input pair tile: 8 channels x 59 packs
        for (int idx = tid; idx < 8 * 59; idx += 256) {
            int c = idx / 59, jj = idx - c * 59;
            const float* row = inb + (size_t)(cc + c) * LS;
            float sc = g_scale[cc + c], sh = g_shift[cc + c];
            int ip0 = base + jj, ip1 = ip0 + 8;
            float v0 = 0.f, v1 = 0.f;
            if ((unsigned)ip0 < (unsigned)Lin) v0 = fmaxf(fmaf(row[ip0], sc, sh), 0.f);
            if ((unsigned)ip1 < (unsigned)Lin) v1 = fmaxf(fmaf(row[ip1], sc, sh), 0.f);
            in_s2[c][jj] = pack2(v0, v1);
        }
        // weights: 64 oc x 32 (c*4+k), duplicated into both halves
        {
            const float* wp = w + ((size_t)oc0 * 256 + cc) * 4;
            for (int idx = tid; idx < 2048; idx += 256) {
                int r = idx & 31, oc = idx >> 5;     // lanes: consecutive r -> coalesced LDG
                float wv = wp[(size_t)oc * 1024 + r];
                w_s2[r][oc] = pack2(wv, wv);
            }
        }
        __syncthreads();
#pragma unroll
        for (int c = 0; c < 8; c++) {
            ull vp[11];
#pragma unroll
            for (int j = 0; j < 11; j++) vp[j] = in_s2[c][tbase + j];
#pragma unroll
            for (int k = 0; k < 4; k++) {
                ull wk = w_s2[c * 4 + k][ocl];
#pragma unroll
                for (int p = 0; p < 8; p++)
                    acc2[p] = ffma2(wk, vp[p + k], acc2[p]);
            }
        }
    }

    // unpack: output local (tbase+p) = lo, (tbase+8+p) = hi
    float a[16];
#pragma unroll
    for (int p = 0; p < 8; p++) unpack2(acc2[p], a[p], a[p + 8]);
    const float bv = bias[oc0 + ocl];
#pragma unroll
    for (int u = 0; u < 16; u++) a[u] += bv;

    if (do_stats) {
        double s = 0.0, q = 0.0;
#pragma unroll
        for (int u = 0; u < 16; u++) {
            int tl = tbase + ((u < 8) ? u : (u + 8 - 8));   // careful: a[u<8]=local tbase+u, a[u>=8]=tbase+8+(u-8)=tbase+u
            tl = tbase + u;                                  // identical mapping
            if (t0 + tl < Lout) { double d = (double)a[u]; s += d; q += d * d; }
        }
        __syncthreads();
        if (tid < 64) { ssum[tid] = 0.0; ssq[tid] = 0.0; }
        __syncthreads();
        atomicAdd(&ssum[ocl], s);
        atomicAdd(&ssq[ocl], q);
        __syncthreads();
        if (tid < 64) {
            atomicAdd(&g_sum[oc0 + tid], ssum[tid]);
            atomicAdd(&g_sumsq[oc0 + tid], ssq[tid]);
        }
    }

    if (mode == 0) {
        __syncthreads();
#pragma unroll
        for (int u = 0; u < 16; u++) o_s[ocl][tbase + u] = a[u];
        __syncthreads();
        float* ob = out + ((size_t)b * ND + oc0) * LS + t0;
        for (int idx = tid; idx < 4096; idx += 256) {
            int oc = idx >> 6, t = idx & 63;
            if (t0 + t < Lout) ob[(size_t)oc * LS + t] = o_s[oc][t];
        }
    } else {
        float* ob = out + (size_t)b * NT * ND + (oc0 + ocl);
#pragma unroll
        for (int u = 0; u < 16; u++) {
            int t = t0 + tbase + u;
            if (t < Lout) ob[(size_t)t * ND] = a[u];
        }
    }
}

// ---------------- BN stats -> scale/shift for next layer; resets stats ----------
__global__ void scaleshift_kernel(const float* __restrict__ g, const float* __restrict__ be, double N)
{
    int c = threadIdx.x;
    double m = g_sum[c] / N;
    double var = g_sumsq[c] / N - m * m;
    double r = 1.0 / sqrt(var + 1e-5);
    double sc = (double)g[c] * r;
    g_scale[c] = (float)sc;
    g_shift[c] = (float)((double)be[c] - m * sc);
    g_sum[c] = 0.0;
    g_sumsq[c] = 0.0;
}

// ---------------- ||codebook_k||^2 ----------------------------------------------
__global__ void cnorm_kernel(const float* __restrict__ cb)
{
    int gw = (blockIdx.x * 256 + threadIdx.x) >> 5;
    int lane = threadIdx.x & 31;
    float s = 0.f;
    const float* row = cb + (size_t)gw * ND;
    for (int d = lane; d < ND; d += 32) { float v = row[d]; s = fmaf(v, v, s); }
#pragma unroll
    for (int off = 16; off; off >>= 1) s += __shfl_xor_sync(0xffffffffu, s, off);
    if (lane == 0) g_cnorm[gw] = s;
}

// ---------------- VQ: argmin via f32x2 GEMM + z_q write + counts + seg sums -----
// block: 64 tokens; thread = (tokg=tid>>4 -> 4 tokens, codeg=tid&15 -> 8 codes)
// f32x2 pairs run along d (even/odd partial sums), folded lo+hi at the end.
__global__ __launch_bounds__(256) void vq_kernel(
    const float* __restrict__ ze, const float* __restrict__ cb, float* __restrict__ zq)
{
    __shared__ __align__(16) float z_s[64][34];
    __shared__ __align__(16) float c_s[128][34];
    __shared__ int sbest[64];

    const int tid = threadIdx.x;
    const int tok0 = blockIdx.x * 64;
    const int tokg = tid >> 4;
    const int codeg = tid & 15;

    float bval[4];
    int bidx[4];
#pragma unroll
    for (int i = 0; i < 4; i++) { bval[i] = 1e30f; bidx[i] = 0x7fffffff; }

    for (int ct = 0; ct < NK; ct += 128) {
        ull acc2[4][8];
#pragma unroll
        for (int i = 0; i < 4; i++)
#pragma unroll
            for (int j = 0; j < 8; j++) acc2[i][j] = 0ull;

        for (int d0 = 0; d0 < ND; d0 += 32) {
            __syncthreads();
            for (int idx = tid; idx < 64 * 16; idx += 256) {
                int r = idx >> 4, dj = (idx & 15) * 2;
                float2 v = *(const float2*)&ze[(size_t)(tok0 + r) * ND + d0 + dj];
                *(float2*)&z_s[r][dj] = v;
            }
            for (int idx = tid; idx < 128 * 16; idx += 256) {
                int r = idx >> 4, dj = (idx & 15) * 2;
                float2 v = *(const float2*)&cb[(size_t)(ct + r) * ND + d0 + dj];
                *(float2*)&c_s[r][dj] = v;
            }
            __syncthreads();
#pragma unroll
            for (int djp = 0; djp < 16; djp++) {
                ull zr[4], cr[8];
#pragma unroll
                for (int i = 0; i < 4; i++) zr[i] = *(const ull*)&z_s[tokg * 4 + i][2 * djp];
#pragma unroll
                for (int j = 0; j < 8; j++) cr[j] = *(const ull*)&c_s[codeg + 16 * j][2 * djp];
#pragma unroll
                for (int i = 0; i < 4; i++)
#pragma unroll
                    for (int j = 0; j < 8; j++)
                        acc2[i][j] = ffma2(zr[i], cr[j], acc2[i][j]);
            }
        }
#pragma unroll
        for (int j = 0; j < 8; j++) {
            int code = ct + codeg + 16 * j;
            float cn = g_cnorm[code];
#pragma unroll
            for (int i = 0; i < 4; i++) {
                float lo, hi;
                unpack2(acc2[i][j], lo, hi);
                float s = fmaf(-2.f, lo + hi, cn);
                if (s < bval[i] || (s == bval[i] && code < bidx[i])) { bval[i] = s; bidx[i] = code; }
            }
        }
    }
    // reduce across the 16 code-lanes sharing each token (tie -> smaller index)
#pragma unroll
    for (int off = 8; off >= 1; off >>= 1) {
#pragma unroll
        for (int i = 0; i < 4; i++) {
            float ov = __shfl_xor_sync(0xffffffffu, bval[i], off);
            int oi = __shfl_xor_sync(0xffffffffu, bidx[i], off);
            if (ov < bval[i] || (ov == bval[i] && oi < bidx[i])) { bval[i] = ov; bidx[i] = oi; }
        }
    }
    if (codeg == 0) {
#pragma unroll
        for (int i = 0; i < 4; i++) sbest[tokg * 4 + i] = bidx[i];
    }
    __syncthreads();
    if (tid < 64) atomicAdd(&g_cnt[sbest[tid]], 1.0f);
    for (int e = tid; e < 64 * ND; e += 256) {
        int r = e >> 8, d = e & 255;
        int code = sbest[r];
        size_t gz = (size_t)(tok0 + r) * ND + d;
        float zev = ze[gz];
        float cbv = cb[(size_t)code * ND + d];
        zq[gz] = zev + (cbv - zev);
        atomicAdd(&g_sumcur[(size_t)code * ND + d], zev);
    }
}

// ---------------- EMA epilogue ---------------------------------------------------
__global__ void ema1_kernel(const float* __restrict__ ecs, float* __restrict__ necs)
{
    __shared__ float red[1024];
    int k = threadIdx.x;
    float ne = ecs[k] * 0.99f + 0.01f * g_cnt[k];
    necs[k] = ne;
    g_cnt[k] = 0.f;
    red[k] = ne;
    __syncthreads();
    for (int off = 512; off; off >>= 1) {
        if (k < off) red[k] += red[k + off];
        __syncthreads();
    }
    if (k == 0) g_n = red[0];
}

__global__ void ema2_kernel(const float* __restrict__ ema_w, const float* __restrict__ necs,
                            float* __restrict__ ncb)
{
    int k = blockIdx.x, d = threadIdx.x;
    float n = g_n;
    float smoothed = (necs[k] + 1e-5f) / (n + 1024.f * 1e-5f) * n;
    size_t idx = (size_t)k * ND + d;
    float nw = ema_w[idx] * 0.99f + 0.01f * g_sumcur[idx];
    ncb[idx] = nw / smoothed;
    g_sumcur[idx] = 0.f;
}

// ---------------- host launcher ---------------------------------------------------
extern "C" void kernel_launch(void* const* d_in, const int* in_sizes, int n_in,
                              void* d_out, int out_size)
{
    const float* X = (const float*)d_in[0];
    const float *W[6], *Bi[6], *G[5], *Be[5];

    bool sig = (in_sizes[3] == 256);
    if (!sig) {
        for (int i = 0; i < 6; i++) { W[i] = (const float*)d_in[1 + 2 * i]; Bi[i] = (const float*)d_in[2 + 2 * i]; }
        for (int i = 0; i < 5; i++) { G[i] = (const float*)d_in[13 + 2 * i]; Be[i] = (const float*)d_in[14 + 2 * i]; }
    } else {
        for (int i = 0; i < 5; i++) {
            W[i]  = (const float*)d_in[1 + 4 * i];
            Bi[i] = (const float*)d_in[2 + 4 * i];
            G[i]  = (const float*)d_in[3 + 4 * i];
            Be[i] = (const float*)d_in[4 + 4 * i];
        }
        W[5] = (const float*)d_in[21];
        Bi[5] = (const float*)d_in[22];
    }
    const float* codebook = (const float*)d_in[23];
    const float* ema_w    = (const float*)d_in[24];
    const float* ecs      = (const float*)d_in[25];

    float* out  = (float*)d_out;
    float* ze   = out;
    float* zq   = out + (size_t)33554432;
    float* ncb  = out + (size_t)67108864;
    float* necs = out + (size_t)67371008;

    float *bufA = nullptr, *bufB = nullptr;
    cudaGetSymbolAddress((void**)&bufA, g_bufA);
    cudaGetSymbolAddress((void**)&bufB, g_bufB);

    dim3 blk(256);
    conv1_kernel<<<dim3(65, 4, 32), blk>>>(X, W[0], Bi[0], bufA);
    scaleshift_kernel<<<1, 256>>>(G[0], Be[0], (double)(32.0 * 4097.0));
    convDD_kernel<<<dim3(64, 4, 32), blk>>>(bufA, W[1], Bi[1], bufB, 4097, 4096, 1, 0, 1);
    scaleshift_kernel<<<1, 256>>>(G[1], Be[1], (double)(32.0 * 4096.0));
    convDD_kernel<<<dim3(65, 4, 32), blk>>>(bufB, W[2], Bi[2], bufA, 4096, 4097, 2, 0, 1);
    scaleshift_kernel<<<1, 256>>>(G[2], Be[2], (double)(32.0 * 4097.0));
    convDD_kernel<<<dim3(64, 4, 32), blk>>>(bufA, W[3], Bi[3], bufB, 4097, 4096, 1, 0, 1);
    scaleshift_kernel<<<1, 256>>>(G[3], Be[3], (double)(32.0 * 4096.0));
    convDD_kernel<<<dim3(65, 4, 32), blk>>>(bufB, W[4], Bi[4], bufA, 4096, 4097, 2, 0, 1);
    scaleshift_kernel<<<1, 256>>>(G[4], Be[4], (double)(32.0 * 4097.0));
    convDD_kernel<<<dim3(64, 4, 32), blk>>>(bufA, W[5], Bi[5], ze, 4097, 4096, 1, 1, 0);

    cnorm_kernel<<<128, 256>>>(codebook);
    vq_kernel<<<2048, 256>>>(ze, codebook, zq);
    ema1_kernel<<<1, 1024>>>(ecs, necs);
    ema2_kernel<<<1024, 256>>>(ema_w, necs, ncb);
}